// round 2
// baseline (speedup 1.0000x reference)
#include <cuda_runtime.h>
#include <math.h>

#define BB   2
#define SS   2048
#define HID  1024
#define NH   16
#define HD   64
#define MTOT (BB*SS)   // 4096

// Scratch (allocation-free: __device__ globals), 16 MB each.
__device__ float g_q[(size_t)MTOT*HID];
__device__ float g_k[(size_t)MTOT*HID];
__device__ float g_v[(size_t)MTOT*HID];
__device__ float g_a[(size_t)MTOT*HID];

// ---------------------------------------------------------------------------
// QKV GEMM: {q,k,v}[z] = x @ W[z], 4096x1024x1024. 128x128 block tile,
// 8x8 per thread, BK=16. RoPE epilogue on z=0,1 (Q,K).
// ---------------------------------------------------------------------------
__device__ __forceinline__ void gemm_body(
    const float* __restrict__ A, const float* __restrict__ W,
    float* __restrict__ C, bool rope)
{
    __shared__ float As[16 * 132];   // transposed A tile [k][m], pad 132
    __shared__ float Bs[16 * 128];   // B tile [k][n]
    __shared__ float invf[32];       // RoPE inverse frequencies

    const int tid = threadIdx.x;
    const int ty = tid >> 4, tx = tid & 15;
    const int m0 = blockIdx.y << 7, n0 = blockIdx.x << 7;

    if (rope && tid < 32) {
        // theta^(-2i/64), computed in double to match fp32 reference to ~1 ulp
        invf[tid] = (float)exp(-((double)(2 * tid) / 64.0) * 9.210340371976184);
    }

    float acc[8][8];
    #pragma unroll
    for (int i = 0; i < 8; i++)
        #pragma unroll
        for (int j = 0; j < 8; j++) acc[i][j] = 0.f;

    for (int k0 = 0; k0 < HID; k0 += 16) {
        __syncthreads();
        // A tile 128x16 -> transposed into As
        #pragma unroll
        for (int it = 0; it < 2; ++it) {
            int id = tid + (it << 8);
            int row = id >> 2, c4 = (id & 3) << 2;
            float4 va = *(const float4*)(A + (size_t)(m0 + row) * HID + k0 + c4);
            As[(c4 + 0) * 132 + row] = va.x;
            As[(c4 + 1) * 132 + row] = va.y;
            As[(c4 + 2) * 132 + row] = va.z;
            As[(c4 + 3) * 132 + row] = va.w;
        }
        // B tile 16x128 direct
        #pragma unroll
        for (int it = 0; it < 2; ++it) {
            int id = tid + (it << 8);
            int row = id >> 5, c4 = (id & 31) << 2;
            *(float4*)&Bs[(row << 7) + c4] =
                *(const float4*)(W + (size_t)(k0 + row) * HID + n0 + c4);
        }
        __syncthreads();

        #pragma unroll
        for (int k = 0; k < 16; ++k) {
            float a[8], b[8];
            *(float4*)&a[0] = *(float4*)&As[k * 132 + (ty << 3)];
            *(float4*)&a[4] = *(float4*)&As[k * 132 + (ty << 3) + 4];
            *(float4*)&b[0] = *(float4*)&Bs[(k << 7) + (tx << 3)];
            *(float4*)&b[4] = *(float4*)&Bs[(k << 7) + (tx << 3) + 4];
            #pragma unroll
            for (int i = 0; i < 8; i++)
                #pragma unroll
                for (int j = 0; j < 8; j++)
                    acc[i][j] += a[i] * b[j];
        }
    }

    // Epilogue
    #pragma unroll
    for (int i = 0; i < 8; i++) {
        int m = m0 + (ty << 3) + i;
        float* cp = C + (size_t)m * HID + n0 + (tx << 3);
        if (rope) {
            float t = (float)(m & (SS - 1));   // position within sequence
            float outv[8];
            #pragma unroll
            for (int j = 0; j < 4; j++) {
                int col = n0 + (tx << 3) + 2 * j;
                int fidx = (col & 63) >> 1;
                float sv, cv;
                sincosf(t * invf[fidx], &sv, &cv);
                float x0 = acc[i][2 * j], x1 = acc[i][2 * j + 1];
                outv[2 * j]     = x0 * cv - x1 * sv;
                outv[2 * j + 1] = x0 * sv + x1 * cv;
            }
            *(float4*)cp       = *(float4*)&outv[0];
            *(float4*)(cp + 4) = *(float4*)&outv[4];
        } else {
            *(float4*)cp       = *(float4*)&acc[i][0];
            *(float4*)(cp + 4) = *(float4*)&acc[i][4];
        }
    }
}

__global__ __launch_bounds__(256, 2) void qkv_kernel(
    const float* __restrict__ x,
    const float* __restrict__ Wq, const float* __restrict__ Wk,
    const float* __restrict__ Wv)
{
    const int z = blockIdx.z;
    const float* W = (z == 0) ? Wq : (z == 1) ? Wk : Wv;
    float*       C = (z == 0) ? g_q : (z == 1) ? g_k : g_v;
    gemm_body(x, W, C, z < 2);
}

__global__ __launch_bounds__(256, 2) void oproj_kernel(
    const float* __restrict__ Wo, float* __restrict__ out)
{
    gemm_body(g_a, Wo, out, false);
}

// ---------------------------------------------------------------------------
// Flash attention: per (q-tile of 128, head, batch). BKV=64, full softmax
// (mask is all-true). 256 threads: S tile 8x4/thread, O tile 8x4/thread.
// Softmax scale (1/8) folded into the Q tile load.
// ---------------------------------------------------------------------------
__global__ __launch_bounds__(256, 2) void flash_kernel()
{
    extern __shared__ float sm[];
    float* Qs = sm;                 // [64 d][132]  (transposed, padded)
    float* Ks = sm + 64 * 132;      // [64 d][68]   (transposed, padded)
    float* Vs = Ks + 64 * 68;       // [64 kv][64 d]
    float* Ps = Vs + 64 * 64;       // [128 q][68]

    const int tid = threadIdx.x;
    const int ty = tid >> 4, tx = tid & 15;
    const int q0 = blockIdx.x << 7;
    const size_t base = (size_t)blockIdx.z * SS * HID + blockIdx.y * HD;
    const float* Qg = g_q + base;
    const float* Kg = g_k + base;
    const float* Vg = g_v + base;
    float* Og = g_a + base;

    // Load Q tile 128x64, transpose via 4x4 register blocks, fold scale 0.125
    #pragma unroll
    for (int it = 0; it < 2; ++it) {
        int id = tid + (it << 8);
        int r0 = (id >> 4) << 2, d0 = (id & 15) << 2;
        const float* gp = Qg + (size_t)(q0 + r0) * HID + d0;
        float4 v0 = *(const float4*)gp;
        float4 v1 = *(const float4*)(gp + HID);
        float4 v2 = *(const float4*)(gp + 2 * HID);
        float4 v3 = *(const float4*)(gp + 3 * HID);
        const float sc = 0.125f;
        *(float4*)&Qs[(d0 + 0) * 132 + r0] = make_float4(v0.x*sc, v1.x*sc, v2.x*sc, v3.x*sc);
        *(float4*)&Qs[(d0 + 1) * 132 + r0] = make_float4(v0.y*sc, v1.y*sc, v2.y*sc, v3.y*sc);
        *(float4*)&Qs[(d0 + 2) * 132 + r0] = make_float4(v0.z*sc, v1.z*sc, v2.z*sc, v3.z*sc);
        *(float4*)&Qs[(d0 + 3) * 132 + r0] = make_float4(v0.w*sc, v1.w*sc, v2.w*sc, v3.w*sc);
    }

    float m_i[8], l_i[8], o[8][4];
    #pragma unroll
    for (int i = 0; i < 8; i++) {
        m_i[i] = -1e30f;
        l_i[i] = 0.f;
        #pragma unroll
        for (int j = 0; j < 4; j++) o[i][j] = 0.f;
    }

    for (int kv0 = 0; kv0 < SS; kv0 += 64) {
        __syncthreads();
        // K tile 64x64 -> transposed
        {
            int r0 = (tid >> 4) << 2, d0 = (tid & 15) << 2;
            const float* gp = Kg + (size_t)(kv0 + r0) * HID + d0;
            float4 v0 = *(const float4*)gp;
            float4 v1 = *(const float4*)(gp + HID);
            float4 v2 = *(const float4*)(gp + 2 * HID);
            float4 v3 = *(const float4*)(gp + 3 * HID);
            *(float4*)&Ks[(d0 + 0) * 68 + r0] = make_float4(v0.x, v1.x, v2.x, v3.x);
            *(float4*)&Ks[(d0 + 1) * 68 + r0] = make_float4(v0.y, v1.y, v2.y, v3.y);
            *(float4*)&Ks[(d0 + 2) * 68 + r0] = make_float4(v0.z, v1.z, v2.z, v3.z);
            *(float4*)&Ks[(d0 + 3) * 68 + r0] = make_float4(v0.w, v1.w, v2.w, v3.w);
        }
        // V tile 64x64 direct
        #pragma unroll
        for (int it = 0; it < 4; ++it) {
            int id = tid + (it << 8);
            int row = id >> 4, c4 = (id & 15) << 2;
            *(float4*)&Vs[(row << 6) + c4] =
                *(const float4*)(Vg + (size_t)(kv0 + row) * HID + c4);
        }
        __syncthreads();

        // S = (Q*scale) K^T : 128x64 tile
        float s[8][4];
        #pragma unroll
        for (int i = 0; i < 8; i++)
            #pragma unroll
            for (int j = 0; j < 4; j++) s[i][j] = 0.f;

        #pragma unroll 8
        for (int d = 0; d < 64; ++d) {
            float a[8], bv[4];
            *(float4*)&a[0]  = *(float4*)&Qs[d * 132 + (ty << 3)];
            *(float4*)&a[4]  = *(float4*)&Qs[d * 132 + (ty << 3) + 4];
            *(float4*)&bv[0] = *(float4*)&Ks[d * 68 + (tx << 2)];
            #pragma unroll
            for (int i = 0; i < 8; i++)
                #pragma unroll
                for (int j = 0; j < 4; j++)
                    s[i][j] += a[i] * bv[j];
        }

        // Online softmax (16 lanes share each row group via xor-shuffle)
        #pragma unroll
        for (int i = 0; i < 8; i++) {
            float mx = fmaxf(fmaxf(s[i][0], s[i][1]), fmaxf(s[i][2], s[i][3]));
            mx = fmaxf(mx, __shfl_xor_sync(0xffffffffu, mx, 8));
            mx = fmaxf(mx, __shfl_xor_sync(0xffffffffu, mx, 4));
            mx = fmaxf(mx, __shfl_xor_sync(0xffffffffu, mx, 2));
            mx = fmaxf(mx, __shfl_xor_sync(0xffffffffu, mx, 1));
            float mnew = fmaxf(m_i[i], mx);
            float fac  = __expf(m_i[i] - mnew);
            m_i[i] = mnew;
            float sum = 0.f;
            #pragma unroll
            for (int j = 0; j < 4; j++) {
                s[i][j] = __expf(s[i][j] - mnew);
                sum += s[i][j];
            }
            sum += __shfl_xor_sync(0xffffffffu, sum, 8);
            sum += __shfl_xor_sync(0xffffffffu, sum, 4);
            sum += __shfl_xor_sync(0xffffffffu, sum, 2);
            sum += __shfl_xor_sync(0xffffffffu, sum, 1);
            l_i[i] = l_i[i] * fac + sum;
            #pragma unroll
            for (int j = 0; j < 4; j++) o[i][j] *= fac;
            *(float4*)&Ps[((ty << 3) + i) * 68 + (tx << 2)] = *(float4*)&s[i][0];
        }
        __syncthreads();

        // O += P V : 128x64
        #pragma unroll 4
        for (int k = 0; k < 64; k += 4) {
            float4 vv0 = *(float4*)&Vs[((k + 0) << 6) + (tx << 2)];
            float4 vv1 = *(float4*)&Vs[((k + 1) << 6) + (tx << 2)];
            float4 vv2 = *(float4*)&Vs[((k + 2) << 6) + (tx << 2)];
            float4 vv3 = *(float4*)&Vs[((k + 3) << 6) + (tx << 2)];
            #pragma unroll
            for (int i = 0; i < 8; i++) {
                float4 p = *(float4*)&Ps[((ty << 3) + i) * 68 + k];
                o[i][0] += p.x * vv0.x; o[i][0] += p.y * vv1.x;
                o[i][0] += p.z * vv2.x; o[i][0] += p.w * vv3.x;
                o[i][1] += p.x * vv0.y; o[i][1] += p.y * vv1.y;
                o[i][1] += p.z * vv2.y; o[i][1] += p.w * vv3.y;
                o[i][2] += p.x * vv0.z; o[i][2] += p.y * vv1.z;
                o[i][2] += p.z * vv2.z; o[i][2] += p.w * vv3.z;
                o[i][3] += p.x * vv0.w; o[i][3] += p.y * vv1.w;
                o[i][3] += p.z * vv2.w; o[i][3] += p.w * vv3.w;
            }
        }
    }

    // Normalize and store
    #pragma unroll
    for (int i = 0; i < 8; i++) {
        float inv_l = 1.0f / l_i[i];
        float4 r;
        r.x = o[i][0] * inv_l; r.y = o[i][1] * inv_l;
        r.z = o[i][2] * inv_l; r.w = o[i][3] * inv_l;
        *(float4*)(Og + (size_t)(q0 + (ty << 3) + i) * HID + (tx << 2)) = r;
    }
}

// ---------------------------------------------------------------------------
extern "C" void kernel_launch(void* const* d_in, const int* in_sizes, int n_in,
                              void* d_out, int out_size)
{
    const float* x  = (const float*)d_in[0];
    const float* Wq = (const float*)d_in[1];
    const float* Wk = (const float*)d_in[2];
    const float* Wv = (const float*)d_in[3];
    const float* Wo = (const float*)d_in[4];
    float* out = (float*)d_out;

    const size_t smem = (64 * 132 + 64 * 68 + 64 * 64 + 128 * 68) * sizeof(float);
    cudaFuncSetAttribute(flash_kernel,
                         cudaFuncAttributeMaxDynamicSharedMemorySize, (int)smem);

    // QKV projections (+RoPE on Q,K)
    qkv_kernel<<<dim3(HID / 128, MTOT / 128, 3), 256>>>(x, Wq, Wk, Wv);
    // Attention
    flash_kernel<<<dim3(SS / 128, NH, BB), 256, smem>>>();
    // Output projection
    oproj_kernel<<<dim3(HID / 128, MTOT / 128, 1), 256>>>(Wo, out);
}

// round 4
// speedup vs baseline: 1.4407x; 1.4407x over previous
#include <cuda_runtime.h>
#include <cuda_bf16.h>
#include <math.h>
#include <stdint.h>

#define BB   2
#define SS   2048
#define HID  1024
#define NH   16
#define HD   64
#define MTOT (BB*SS)   // 4096

// ---------------- scratch (__device__ globals; no allocs) -------------------
__device__ float g_q[(size_t)MTOT*HID];
__device__ float g_k[(size_t)MTOT*HID];
__device__ float g_v[(size_t)MTOT*HID];
__device__ float g_a[(size_t)MTOT*HID];
__device__ __nv_bfloat16 g_xh[(size_t)MTOT*HID];
__device__ __nv_bfloat16 g_xl[(size_t)MTOT*HID];
__device__ __nv_bfloat16 g_wth[(size_t)4*HID*HID];  // W^T [N][K] hi
__device__ __nv_bfloat16 g_wtl[(size_t)4*HID*HID];  // W^T [N][K] lo

// ---------------- PTX helpers (compute_100-legal only) ----------------------
__device__ __forceinline__ uint32_t smem_u32(const void* p) {
    uint32_t a;
    asm("{ .reg .u64 t; cvta.to.shared.u64 t, %1; cvt.u32.u64 %0, t; }"
        : "=r"(a) : "l"(p));
    return a;
}
__device__ __forceinline__ uint32_t swz(uint32_t bo) {
    return bo ^ ((bo >> 3) & 0x70);   // SW128: 16B-chunk permute within 128B row
}
__device__ __forceinline__ void ldsm4(uint32_t* r, uint32_t addr) {
    asm volatile("ldmatrix.sync.aligned.m8n8.x4.shared.b16 {%0,%1,%2,%3}, [%4];"
                 : "=r"(r[0]), "=r"(r[1]), "=r"(r[2]), "=r"(r[3]) : "r"(addr));
}
__device__ __forceinline__ void mma16816(float* d, const uint32_t* a,
                                         const uint32_t* b) {
    asm volatile(
        "mma.sync.aligned.m16n8k16.row.col.f32.bf16.bf16.f32 "
        "{%0,%1,%2,%3}, {%4,%5,%6,%7}, {%8,%9}, {%0,%1,%2,%3};"
        : "+f"(d[0]), "+f"(d[1]), "+f"(d[2]), "+f"(d[3])
        : "r"(a[0]), "r"(a[1]), "r"(a[2]), "r"(a[3]), "r"(b[0]), "r"(b[1]));
}
#define CP_ASYNC16(dst, src) \
    asm volatile("cp.async.cg.shared.global [%0], [%1], 16;" :: "r"(dst), "l"(src))
#define CP_COMMIT() asm volatile("cp.async.commit_group;" ::: "memory")
#define CP_WAIT0()  asm volatile("cp.async.wait_group 0;" ::: "memory")

// ---------------- prep: split fp32 -> bf16 hi/lo ----------------------------
__device__ __forceinline__ void split_body(const float* __restrict__ src,
                                           __nv_bfloat16* __restrict__ hi,
                                           __nv_bfloat16* __restrict__ lo) {
    size_t i = ((size_t)blockIdx.x * blockDim.x + threadIdx.x) * 4;
    float4 v = *(const float4*)(src + i);
    __nv_bfloat16 h0 = __float2bfloat16_rn(v.x);
    __nv_bfloat16 h1 = __float2bfloat16_rn(v.y);
    __nv_bfloat16 h2 = __float2bfloat16_rn(v.z);
    __nv_bfloat16 h3 = __float2bfloat16_rn(v.w);
    __nv_bfloat162* hp = (__nv_bfloat162*)(hi + i);
    hp[0] = __nv_bfloat162(h0, h1);
    hp[1] = __nv_bfloat162(h2, h3);
    __nv_bfloat162* lp = (__nv_bfloat162*)(lo + i);
    lp[0] = __nv_bfloat162(__float2bfloat16_rn(v.x - __bfloat162float(h0)),
                           __float2bfloat16_rn(v.y - __bfloat162float(h1)));
    lp[1] = __nv_bfloat162(__float2bfloat16_rn(v.z - __bfloat162float(h2)),
                           __float2bfloat16_rn(v.w - __bfloat162float(h3)));
}
__global__ void split_x_kernel(const float* __restrict__ src) {
    split_body(src, g_xh, g_xl);
}
__global__ void split_a_kernel() {
    split_body(g_a, g_xh, g_xl);
}

// ---------------- prep: transpose + split weights ---------------------------
__global__ void tsplit_w_kernel(const float* __restrict__ Wq,
                                const float* __restrict__ Wk,
                                const float* __restrict__ Wv,
                                const float* __restrict__ Wo) {
    const int z = blockIdx.z;
    const float* W = (z == 0) ? Wq : (z == 1) ? Wk : (z == 2) ? Wv : Wo;
    __nv_bfloat16* oh = g_wth + (size_t)z * HID * HID;
    __nv_bfloat16* ol = g_wtl + (size_t)z * HID * HID;
    __shared__ float t[32][33];
    const int n0 = blockIdx.x << 5, k0 = blockIdx.y << 5;
    const int tx = threadIdx.x, ty = threadIdx.y;
    #pragma unroll
    for (int r = 0; r < 4; r++)
        t[ty + 8 * r][tx] = W[(size_t)(k0 + ty + 8 * r) * HID + n0 + tx];
    __syncthreads();
    #pragma unroll
    for (int r = 0; r < 4; r++) {
        float v = t[tx][ty + 8 * r];
        __nv_bfloat16 h = __float2bfloat16_rn(v);
        size_t o = (size_t)(n0 + ty + 8 * r) * HID + k0 + tx;
        oh[o] = h;
        ol[o] = __float2bfloat16_rn(v - __bfloat162float(h));
    }
}

// ---------------- mma.sync GEMM: C[128x128] = A@W^T (split bf16) ------------
// Stage (64 KB): Ah @0, Al @16K, Bh @32K, Bl @48K; each 128 rows x 128 B (K=64
// bf16), SW128-swizzled. Two stages, cp.async double buffering.
#define STG_BYTES 65536
#define MM_SMEM   (2 * STG_BYTES)

__device__ __forceinline__ void stage_load(
    const __nv_bfloat16* __restrict__ Ah, const __nv_bfloat16* __restrict__ Al,
    const __nv_bfloat16* __restrict__ Bh, const __nv_bfloat16* __restrict__ Bl,
    int m0, int n0, int k0, uint32_t sst, int tid)
{
    #pragma unroll
    for (int it = 0; it < 2; ++it) {
        int idx = tid + (it << 9);          // 0..1023
        int row = idx >> 3, c = idx & 7;    // 128 rows x 8 16B-chunks
        uint32_t so = swz((row << 7) + (c << 4));
        size_t goA = (size_t)(m0 + row) * HID + k0 + (c << 3);
        size_t goB = (size_t)(n0 + row) * HID + k0 + (c << 3);
        CP_ASYNC16(sst + so,              Ah + goA);
        CP_ASYNC16(sst + 16384 + so,      Al + goA);
        CP_ASYNC16(sst + 32768 + so,      Bh + goB);
        CP_ASYNC16(sst + 49152 + so,      Bl + goB);
    }
}

__device__ __forceinline__ void mm_body(
    const __nv_bfloat16* __restrict__ Ah, const __nv_bfloat16* __restrict__ Al,
    const __nv_bfloat16* __restrict__ Bh, const __nv_bfloat16* __restrict__ Bl,
    float* __restrict__ C, bool rope)
{
    extern __shared__ char dsm[];
    __shared__ float invf[32];
    const uint32_t sb = smem_u32(dsm);
    const int tid = threadIdx.x, wid = tid >> 5, lane = tid & 31;
    const int m0 = blockIdx.y << 7, n0 = blockIdx.x << 7;
    const int wm = (wid & 3) << 5;      // warp row offset (2 m-tiles of 16)
    const int wn = (wid >> 2) << 5;     // warp col offset (4 n-tiles of 8)

    if (rope && tid < 32)
        invf[tid] = (float)exp(-((double)(2 * tid) / 64.0) * 9.210340371976184);

    float d[2][4][4];
    #pragma unroll
    for (int mt = 0; mt < 2; mt++)
        #pragma unroll
        for (int nt = 0; nt < 4; nt++)
            #pragma unroll
            for (int r = 0; r < 4; r++) d[mt][nt][r] = 0.f;

    // lane-derived ldmatrix address components
    const uint32_t a_row = wm + (lane & 7) + (((lane >> 3) & 1) << 3);
    const uint32_t a_cb  = (lane >> 4) << 4;                   // col bytes (+8 cols)
    const uint32_t b_row = wn + (lane & 7) + (((lane >> 4) & 1) << 3);
    const uint32_t b_cb  = ((lane >> 3) & 1) << 4;

    stage_load(Ah, Al, Bh, Bl, m0, n0, 0, sb, tid);
    CP_COMMIT();

    for (int c = 0; c < 16; ++c) {
        const uint32_t st = sb + (uint32_t)(c & 1) * STG_BYTES;
        CP_WAIT0();
        __syncthreads();
        if (c + 1 < 16) {
            stage_load(Ah, Al, Bh, Bl, m0, n0, (c + 1) << 6,
                       sb + (uint32_t)((c + 1) & 1) * STG_BYTES, tid);
            CP_COMMIT();
        }
        #pragma unroll
        for (int ks = 0; ks < 4; ++ks) {
            const uint32_t kb = (uint32_t)(ks << 5);   // col bytes for this k16
            uint32_t ah[2][4], al[2][4], bh[2][4], bl[2][4];
            #pragma unroll
            for (int mt = 0; mt < 2; mt++) {
                uint32_t ao = swz(((a_row + (mt << 4)) << 7) + kb + a_cb);
                ldsm4(ah[mt], st + ao);
                ldsm4(al[mt], st + 16384 + ao);
            }
            #pragma unroll
            for (int np = 0; np < 2; np++) {
                uint32_t bo = swz(((b_row + (np << 4)) << 7) + kb + b_cb);
                ldsm4(bh[np], st + 32768 + bo);
                ldsm4(bl[np], st + 49152 + bo);
            }
            #pragma unroll
            for (int mt = 0; mt < 2; mt++)
                #pragma unroll
                for (int nt = 0; nt < 4; nt++) {
                    const uint32_t* bhp = &bh[nt >> 1][(nt & 1) << 1];
                    const uint32_t* blp = &bl[nt >> 1][(nt & 1) << 1];
                    mma16816(d[mt][nt], ah[mt], bhp);
                    mma16816(d[mt][nt], al[mt], bhp);
                    mma16816(d[mt][nt], ah[mt], blp);
                }
        }
    }

    // Epilogue: thread holds C[r0][col..col+1] (d0,d1) and C[r0+8][..] (d2,d3)
    #pragma unroll
    for (int mt = 0; mt < 2; mt++) {
        const int r0 = m0 + wm + (mt << 4) + (lane >> 2);
        #pragma unroll
        for (int nt = 0; nt < 4; nt++) {
            const int col = n0 + wn + (nt << 3) + ((lane & 3) << 1);
            float* v = d[mt][nt];
            if (rope) {
                const float fr = invf[(col & 63) >> 1];
                float sv, cv;
                sincosf((float)(r0 & (SS - 1)) * fr, &sv, &cv);
                float o0 = v[0] * cv - v[1] * sv;
                float o1 = v[0] * sv + v[1] * cv;
                sincosf((float)((r0 + 8) & (SS - 1)) * fr, &sv, &cv);
                float o2 = v[2] * cv - v[3] * sv;
                float o3 = v[2] * sv + v[3] * cv;
                *(float2*)(C + (size_t)r0 * HID + col)       = make_float2(o0, o1);
                *(float2*)(C + (size_t)(r0 + 8) * HID + col) = make_float2(o2, o3);
            } else {
                *(float2*)(C + (size_t)r0 * HID + col)       = make_float2(v[0], v[1]);
                *(float2*)(C + (size_t)(r0 + 8) * HID + col) = make_float2(v[2], v[3]);
            }
        }
    }
}

__global__ __launch_bounds__(512, 1) void qkv_mm_kernel() {
    const int z = blockIdx.z;
    float* C = (z == 0) ? g_q : (z == 1) ? g_k : g_v;
    mm_body(g_xh, g_xl,
            g_wth + (size_t)z * HID * HID, g_wtl + (size_t)z * HID * HID,
            C, z < 2);
}
__global__ __launch_bounds__(512, 1) void oproj_mm_kernel(float* __restrict__ out) {
    mm_body(g_xh, g_xl,
            g_wth + (size_t)3 * HID * HID, g_wtl + (size_t)3 * HID * HID,
            out, false);
}

// ---------------- flash attention (unchanged from R2, fp32) -----------------
__global__ __launch_bounds__(256, 2) void flash_kernel()
{
    extern __shared__ float sm[];
    float* Qs = sm;                 // [64 d][132]
    float* Ks = sm + 64 * 132;      // [64 d][68]
    float* Vs = Ks + 64 * 68;       // [64 kv][64 d]
    float* Ps = Vs + 64 * 64;       // [128 q][68]

    const int tid = threadIdx.x;
    const int ty = tid >> 4, tx = tid & 15;
    const int q0 = blockIdx.x << 7;
    const size_t base = (size_t)blockIdx.z * SS * HID + blockIdx.y * HD;
    const float* Qg = g_q + base;
    const float* Kg = g_k + base;
    const float* Vg = g_v + base;
    float* Og = g_a + base;

    #pragma unroll
    for (int it = 0; it < 2; ++it) {
        int id = tid + (it << 8);
        int r0 = (id >> 4) << 2, d0 = (id & 15) << 2;
        const float* gp = Qg + (size_t)(q0 + r0) * HID + d0;
        float4 v0 = *(const float4*)gp;
        float4 v1 = *(const float4*)(gp + HID);
        float4 v2 = *(const float4*)(gp + 2 * HID);
        float4 v3 = *(const float4*)(gp + 3 * HID);
        const float sc = 0.125f;
        *(float4*)&Qs[(d0 + 0) * 132 + r0] = make_float4(v0.x*sc, v1.x*sc, v2.x*sc, v3.x*sc);
        *(float4*)&Qs[(d0 + 1) * 132 + r0] = make_float4(v0.y*sc, v1.y*sc, v2.y*sc, v3.y*sc);
        *(float4*)&Qs[(d0 + 2) * 132 + r0] = make_float4(v0.z*sc, v1.z*sc, v2.z*sc, v3.z*sc);
        *(float4*)&Qs[(d0 + 3) * 132 + r0] = make_float4(v0.w*sc, v1.w*sc, v2.w*sc, v3.w*sc);
    }

    float m_i[8], l_i[8], o[8][4];
    #pragma unroll
    for (int i = 0; i < 8; i++) {
        m_i[i] = -1e30f;
        l_i[i] = 0.f;
        #pragma unroll
        for (int j = 0; j < 4; j++) o[i][j] = 0.f;
    }

    for (int kv0 = 0; kv0 < SS; kv0 += 64) {
        __syncthreads();
        {
            int r0 = (tid >> 4) << 2, d0 = (tid & 15) << 2;
            const float* gp = Kg + (size_t)(kv0 + r0) * HID + d0;
            float4 v0 = *(const float4*)gp;
            float4 v1 = *(const float4*)(gp + HID);
            float4 v2 = *(const float4*)(gp + 2 * HID);
            float4 v3 = *(const float4*)(gp + 3 * HID);
            *(float4*)&Ks[(d0 + 0) * 68 + r0] = make_float4(v0.x, v1.x, v2.x, v3.x);
            *(float4*)&Ks[(d0 + 1) * 68 + r0] = make_float4(v0.y, v1.y, v2.y, v3.y);
            *(float4*)&Ks[(d0 + 2) * 68 + r0] = make_float4(v0.z, v1.z, v2.z, v3.z);
            *(float4*)&Ks[(d0 + 3) * 68 + r0] = make_float4(v0.w, v1.w, v2.w, v3.w);
        }
        #pragma unroll
        for (int it = 0; it < 4; ++it) {
            int id = tid + (it << 8);
            int row = id >> 4, c4 = (id & 15) << 2;
            *(float4*)&Vs[(row << 6) + c4] =
                *(const float4*)(Vg + (size_t)(kv0 + row) * HID + c4);
        }
        __syncthreads();

        float s[8][4];
        #pragma unroll
        for (int i = 0; i < 8; i++)
            #pragma unroll
            for (int j = 0; j < 4; j++) s[i][j] = 0.f;

        #pragma unroll 8
        for (int dd = 0; dd < 64; ++dd) {
            float a[8], bv[4];
            *(float4*)&a[0]  = *(float4*)&Qs[dd * 132 + (ty << 3)];
            *(float4*)&a[4]  = *(float4*)&Qs[dd * 132 + (ty << 3) + 4];
            *(float4*)&bv[0] = *(float4*)&Ks[dd * 68 + (tx << 2)];
            #pragma unroll
            for (int i = 0; i < 8; i++)
                #pragma unroll
                for (int j = 0; j < 4; j++)
                    s[i][j] += a[i] * bv[j];
        }

        #pragma unroll
        for (int i = 0; i < 8; i++) {
            float mx = fmaxf(fmaxf(s[i][0], s[i][1]), fmaxf(s[i][2], s[i][3]));
            mx = fmaxf(mx, __shfl_xor_sync(0xffffffffu, mx, 8));
            mx = fmaxf(mx, __shfl_xor_sync(0xffffffffu, mx, 4));
            mx = fmaxf(mx, __shfl_xor_sync(0xffffffffu, mx, 2));
            mx = fmaxf(mx, __shfl_xor_sync(0xffffffffu, mx, 1));
            float mnew = fmaxf(m_i[i], mx);
            float fac  = __expf(m_i[i] - mnew);
            m_i[i] = mnew;
            float sum = 0.f;
            #pragma unroll
            for (int j = 0; j < 4; j++) {
                s[i][j] = __expf(s[i][j] - mnew);
                sum += s[i][j];
            }
            sum += __shfl_xor_sync(0xffffffffu, sum, 8);
            sum += __shfl_xor_sync(0xffffffffu, sum, 4);
            sum += __shfl_xor_sync(0xffffffffu, sum, 2);
            sum += __shfl_xor_sync(0xffffffffu, sum, 1);
            l_i[i] = l_i[i] * fac + sum;
            #pragma unroll
            for (int j = 0; j < 4; j++) o[i][j] *= fac;
            *(float4*)&Ps[((ty << 3) + i) * 68 + (tx << 2)] = *(float4*)&s[i][0];
        }
        __syncthreads();

        #pragma unroll 4
        for (int k = 0; k < 64; k += 4) {
            float4 vv0 = *(float4*)&Vs[((k + 0) << 6) + (tx << 2)];
            float4 vv1 = *(float4*)&Vs[((k + 1) << 6) + (tx << 2)];
            float4 vv2 = *(float4*)&Vs[((k + 2) << 6) + (tx << 2)];
            float4 vv3 = *(float4*)&Vs[((k + 3) << 6) + (tx << 2)];
            #pragma unroll
            for (int i = 0; i < 8; i++) {
                float4 p = *(float4*)&Ps[((ty << 3) + i) * 68 + k];
                o[i][0] += p.x * vv0.x; o[i][0] += p.y * vv1.x;
                o[i][0] += p.z * vv2.x; o[i][0] += p.w * vv3.x;
                o[i][1] += p.x * vv0.y; o[i][1] += p.y * vv1.y;
                o[i][1] += p.z * vv2.y; o[i][1] += p.w * vv3.y;
                o[i][2] += p.x * vv0.z; o[i][2] += p.y * vv1.z;
                o[i][2] += p.z * vv2.z; o[i][2] += p.w * vv3.z;
                o[i][3] += p.x * vv0.w; o[i][3] += p.y * vv1.w;
                o[i][3] += p.z * vv2.w; o[i][3] += p.w * vv3.w;
            }
        }
    }

    #pragma unroll
    for (int i = 0; i < 8; i++) {
        float inv_l = 1.0f / l_i[i];
        float4 r;
        r.x = o[i][0] * inv_l; r.y = o[i][1] * inv_l;
        r.z = o[i][2] * inv_l; r.w = o[i][3] * inv_l;
        *(float4*)(Og + (size_t)(q0 + (ty << 3) + i) * HID + (tx << 2)) = r;
    }
}

// ---------------------------------------------------------------------------
extern "C" void kernel_launch(void* const* d_in, const int* in_sizes, int n_in,
                              void* d_out, int out_size)
{
    const float* x  = (const float*)d_in[0];
    const float* Wq = (const float*)d_in[1];
    const float* Wk = (const float*)d_in[2];
    const float* Wv = (const float*)d_in[3];
    const float* Wo = (const float*)d_in[4];
    float* out = (float*)d_out;

    const size_t smemF = (64 * 132 + 64 * 68 + 64 * 64 + 128 * 68) * sizeof(float);
    cudaFuncSetAttribute(flash_kernel,
                         cudaFuncAttributeMaxDynamicSharedMemorySize, (int)smemF);
    cudaFuncSetAttribute(qkv_mm_kernel,
                         cudaFuncAttributeMaxDynamicSharedMemorySize, MM_SMEM);
    cudaFuncSetAttribute(oproj_mm_kernel,
                         cudaFuncAttributeMaxDynamicSharedMemorySize, MM_SMEM);

    // prep: split x, transpose+split weights
    split_x_kernel<<<4096, 256>>>(x);
    tsplit_w_kernel<<<dim3(32, 32, 4), dim3(32, 8)>>>(Wq, Wk, Wv, Wo);
    // QKV projections (+RoPE) via mma.sync
    qkv_mm_kernel<<<dim3(HID / 128, MTOT / 128, 3), 512, MM_SMEM>>>();
    // attention (fp32 flash)
    flash_kernel<<<dim3(SS / 128, NH, BB), 256, smemF>>>();
    // split attention output, then O-projection via mma.sync
    split_a_kernel<<<4096, 256>>>();
    oproj_mm_kernel<<<dim3(HID / 128, MTOT / 128, 1), 512, MM_SMEM>>>(out);
}